// round 11
// baseline (speedup 1.0000x reference)
#include <cuda_runtime.h>
#include <math.h>

// Shapes (fixed for this problem)
#define B_ 4
#define P_ 32768
#define C_ 8
#define F_ 32
#define D_ 64
#define H_ 64

#define TP 128        // points per CTA tile
#define XLD 65        // padded row stride (floats) for activation tiles (bank-conflict-free)

// ---- precomputed per-(b,c) data (tiny scratch; __device__ globals, no allocs) ----
__device__ float g_M[B_ * C_ * 3 * H_];   // M[b,c][i][h] = (W_feat @ z[b,c] @ W0_mid)[i,h]
__device__ float g_zi[B_ * C_ * H_];      // zi_proj[b,c][h] = z_inv @ W0[65:129] + b0
__device__ float g_G[16];                 // G = W_feat @ W_feat^T (3x3, padded)

// ---- shared memory layout (in floats) ----
#define OFF_XS   0
#define OFF_HS   (TP * XLD)                 // 8320
#define OFF_WA   (2 * TP * XLD)             // 16640
#define OFF_WB   (OFF_WA + H_ * H_)         // 20736
#define OFF_QS   (OFF_WB + H_ * H_)         // 24832  (q0,q1,q2,s per point)
#define OFF_M    (OFF_QS + TP * 4)          // 25344
#define OFF_ZI   (OFF_M + C_ * 3 * H_)      // 26880
#define OFF_W0   (OFF_ZI + C_ * H_)         // 27392  (W0 row 0)
#define OFF_BA   (OFF_W0 + H_)              // 27456  (all 5 ba rows)
#define OFF_BB   (OFF_BA + 5 * H_)          // 27776
#define OFF_WOUT (OFF_BB + 5 * H_)          // 28096
#define OFF_G    (OFF_WOUT + H_)            // 28160
#define OFF_POS  (OFF_G + 16)               // 28176  (pos[3], bout)
#define SMEM_FLOATS (OFF_POS + 4)           // 28180
#define SMEM_BYTES  (SMEM_FLOATS * 4)       // 112720 B -> 2 CTAs/SM

// =====================================================================
// Precompute kernel: 32 blocks (one per (b,c)), 64 threads (h index)
// =====================================================================
__global__ void vson_precompute_kernel(const float* __restrict__ z,
                                       const float* __restrict__ W_feat,
                                       const float* __restrict__ W_dir,
                                       const float* __restrict__ W0,
                                       const float* __restrict__ b0) {
    __shared__ float s_zinv[D_];
    __shared__ float s_Z0[F_ * H_];

    const int bc = blockIdx.x;          // b*C + c
    const int e = threadIdx.x;          // 0..63
    const float* zb = z + bc * F_ * D_; // z[b,c] : (F, D) row-major

    // z_inv[e] = sum_f z[f,e] * (sum_d z[f,d] * W_dir[d,e])
    float zi = 0.f;
    for (int f = 0; f < F_; f++) {
        float zd = 0.f;
        for (int d = 0; d < D_; d++) zd += zb[f * D_ + d] * W_dir[d * D_ + e];
        zi += zb[f * D_ + e] * zd;
    }
    s_zinv[e] = zi;
    __syncthreads();

    // zi_proj[h] = sum_d z_inv[d] * W0[1+D+d, h] + b0[h]
    {
        float zp = b0[e];
        for (int d = 0; d < D_; d++) zp += s_zinv[d] * W0[(1 + D_ + d) * H_ + e];
        g_zi[bc * H_ + e] = zp;
    }

    // Z0[f,h] = sum_d z[f,d] * W0[1+d, h]
    for (int f = 0; f < F_; f++) {
        float s = 0.f;
        for (int d = 0; d < D_; d++) s += zb[f * D_ + d] * W0[(1 + d) * H_ + e];
        s_Z0[f * H_ + e] = s;
    }
    __syncthreads();

    // M[i,h] = sum_f W_feat[i,f] * Z0[f,h]
    for (int i = 0; i < 3; i++) {
        float s = 0.f;
        for (int f = 0; f < F_; f++) s += W_feat[i * F_ + f] * s_Z0[f * H_ + e];
        g_M[(bc * 3 + i) * H_ + e] = s;
    }

    // G (3x3) once
    if (bc == 0 && e < 9) {
        int i = e / 3, j = e % 3;
        float s = 0.f;
        for (int f = 0; f < F_; f++) s += W_feat[i * F_ + f] * W_feat[j * F_ + f];
        g_G[e] = s;
    }
}

// =====================================================================
// Main kernel helpers
// =====================================================================
__device__ __forceinline__ void store4(float* dst, float4 v) {
    dst[0] = v.x; dst[1] = v.y; dst[2] = v.z; dst[3] = v.w;
}

// acc[i] += act(in[rb[i]+k]) * W[k][col..col+3]  over k=0..63
// RELU=true applies relu to the activation read; RELU=false consumes raw
// (used when the producer already stored relu'd values).
template <bool RELU>
__device__ __forceinline__ void mm64(const float* __restrict__ smem,
                                     int in_off, int w_off,
                                     const int rb[8], int col,
                                     float4 acc[8]) {
#pragma unroll 4
    for (int k = 0; k < H_; k++) {
        float4 w = *(const float4*)(smem + w_off + k * H_ + col);
#pragma unroll
        for (int i = 0; i < 8; i++) {
            float r = smem[in_off + rb[i] + k];
            if (RELU) r = fmaxf(r, 0.f);
            acc[i].x += r * w.x;
            acc[i].y += r * w.y;
            acc[i].z += r * w.z;
            acc[i].w += r * w.w;
        }
    }
}

// =====================================================================
// Main decoder kernel: grid (P/TP, B), 256 threads
// Thread tile: 8 points x 4 columns (tj = tid&15 -> cols, tp = tid>>4 -> rows)
// =====================================================================
__global__ __launch_bounds__(256)
void vson_decoder_kernel(const float* __restrict__ p,
                         const float* __restrict__ pos,
                         const float* __restrict__ W0,
                         const float* __restrict__ Wa,
                         const float* __restrict__ ba,
                         const float* __restrict__ Wb,
                         const float* __restrict__ bb,
                         const float* __restrict__ Wout,
                         const float* __restrict__ bout,
                         float* __restrict__ out) {
    extern __shared__ float sm[];
    const int tid = threadIdx.x;
    const int b = blockIdx.y;
    const int p0 = blockIdx.x * TP;

    // ---- stage block-0 weights + misc into shared ----
    {
        const float4* sa = (const float4*)Wa;   // layer 0
        const float4* sb = (const float4*)Wb;
        float4* dA = (float4*)&sm[OFF_WA];
        float4* dB = (float4*)&sm[OFF_WB];
        for (int i = tid; i < (H_ * H_) / 4; i += 256) { dA[i] = sa[i]; dB[i] = sb[i]; }
    }
    for (int i = tid; i < C_ * 3 * H_; i += 256) sm[OFF_M + i] = g_M[b * C_ * 3 * H_ + i];
    for (int i = tid; i < C_ * H_; i += 256)     sm[OFF_ZI + i] = g_zi[b * C_ * H_ + i];
    for (int i = tid; i < 5 * H_; i += 256) { sm[OFF_BA + i] = ba[i]; sm[OFF_BB + i] = bb[i]; }
    if (tid < H_) { sm[OFF_W0 + tid] = W0[tid]; sm[OFF_WOUT + tid] = Wout[tid]; }
    if (tid < 9) sm[OFF_G + tid] = g_G[tid];
    if (tid < 3) sm[OFF_POS + tid] = pos[b * 3 + tid];
    if (tid == 0) sm[OFF_POS + 3] = bout[0];
    __syncthreads();

    // ---- per-point q (centered+clamped) and scalar s = |p_ext|^2 ----
    if (tid < TP) {
        const int pt = p0 + tid;
        const float* pp = p + ((size_t)b * P_ + pt) * 3;
        float q0 = pp[0] - sm[OFF_POS + 0];
        float q1 = pp[1] - sm[OFF_POS + 1];
        float q2 = pp[2] - sm[OFF_POS + 2];
        float n = sqrtf(q0 * q0 + q1 * q1 + q2 * q2);
        if (n > 0.5f) { float sc = 0.5f / n; q0 *= sc; q1 *= sc; q2 *= sc; }
        const float* G = &sm[OFF_G];
        float s = G[0] * q0 * q0 + G[4] * q1 * q1 + G[8] * q2 * q2
                + (G[1] + G[3]) * q0 * q1
                + (G[2] + G[6]) * q0 * q2
                + (G[5] + G[7]) * q1 * q2;
        ((float4*)&sm[OFF_QS])[tid] = make_float4(q0, q1, q2, s);
    }
    __syncthreads();

    const int tj = tid & 15;
    const int tp = tid >> 4;
    const int col = 4 * tj;
    int rb[8];
#pragma unroll
    for (int i = 0; i < 8; i++) rb[i] = (8 * tp + i) * XLD;

    float4 pool[8];

    // =================== block 0 over C=8, with max-pool ===================
    for (int c = 0; c < C_; c++) {
        // X-stage: x = s*W0row0 + q.M[c] + zi_proj[c]   (raw x kept for residual)
        {
            float4 w0 = *(const float4*)&sm[OFF_W0 + col];
            float4 m0 = *(const float4*)&sm[OFF_M + (c * 3 + 0) * H_ + col];
            float4 m1 = *(const float4*)&sm[OFF_M + (c * 3 + 1) * H_ + col];
            float4 m2 = *(const float4*)&sm[OFF_M + (c * 3 + 2) * H_ + col];
            float4 zz = *(const float4*)&sm[OFF_ZI + c * H_ + col];
#pragma unroll
            for (int i = 0; i < 8; i++) {
                float4 q = ((const float4*)&sm[OFF_QS])[8 * tp + i];
                float4 v;
                v.x = q.w * w0.x + q.x * m0.x + q.y * m1.x + q.z * m2.x + zz.x;
                v.y = q.w * w0.y + q.x * m0.y + q.y * m1.y + q.z * m2.y + zz.y;
                v.z = q.w * w0.z + q.x * m0.z + q.y * m1.z + q.z * m2.z + zz.z;
                v.w = q.w * w0.w + q.x * m0.w + q.y * m1.w + q.z * m2.w + zz.w;
                store4(&sm[OFF_XS + rb[i] + col], v);
            }
        }
        __syncthreads();

        // H-stage: h = relu(x) @ Wa0 + ba0 ; store relu(h) (h only consumed via relu)
        float4 acc[8];
        {
            float4 bv = *(const float4*)&sm[OFF_BA + col];
#pragma unroll
            for (int i = 0; i < 8; i++) acc[i] = bv;
        }
        mm64<true>(sm, OFF_XS, OFF_WA, rb, col, acc);
#pragma unroll
        for (int i = 0; i < 8; i++) {
            float4 rv = make_float4(fmaxf(acc[i].x, 0.f), fmaxf(acc[i].y, 0.f),
                                    fmaxf(acc[i].z, 0.f), fmaxf(acc[i].w, 0.f));
            store4(&sm[OFF_HS + rb[i] + col], rv);
        }
        __syncthreads();

        // Y-stage: y = relu(h) @ Wb0 + bb0 + x ; pool = max(pool, y)
        {
            float4 bv = *(const float4*)&sm[OFF_BB + col];
#pragma unroll
            for (int i = 0; i < 8; i++) {
                acc[i].x = sm[OFF_XS + rb[i] + col + 0] + bv.x;
                acc[i].y = sm[OFF_XS + rb[i] + col + 1] + bv.y;
                acc[i].z = sm[OFF_XS + rb[i] + col + 2] + bv.z;
                acc[i].w = sm[OFF_XS + rb[i] + col + 3] + bv.w;
            }
        }
        mm64<false>(sm, OFF_HS, OFF_WB, rb, col, acc);  // HS already relu'd
        if (c == 0) {
#pragma unroll
            for (int i = 0; i < 8; i++) pool[i] = acc[i];
        } else {
#pragma unroll
            for (int i = 0; i < 8; i++) {
                pool[i].x = fmaxf(pool[i].x, acc[i].x);
                pool[i].y = fmaxf(pool[i].y, acc[i].y);
                pool[i].z = fmaxf(pool[i].z, acc[i].z);
                pool[i].w = fmaxf(pool[i].w, acc[i].w);
            }
        }
        // no sync needed here: next X-stage writes only this thread's own (p,col)
        // elements of XS; other threads' Y-stages read only HS + their own XS,
        // and H-stage (which rewrites HS) sits behind the post-X-stage barrier.
    }

    // pooled -> xs
#pragma unroll
    for (int i = 0; i < 8; i++) store4(&sm[OFF_XS + rb[i] + col], pool[i]);
    __syncthreads();

    // =================== residual blocks 1..4 ===================
    for (int l = 1; l < 5; l++) {
        __syncthreads();  // orders prior Y xs-writes & WB reads vs. restage
        {
            const float4* sa = (const float4*)(Wa + l * H_ * H_);
            const float4* sb = (const float4*)(Wb + l * H_ * H_);
            float4* dA = (float4*)&sm[OFF_WA];
            float4* dB = (float4*)&sm[OFF_WB];
            for (int i = tid; i < (H_ * H_) / 4; i += 256) { dA[i] = sa[i]; dB[i] = sb[i]; }
        }
        __syncthreads();

        // H-stage: store relu(h)
        float4 acc[8];
        {
            float4 bv = *(const float4*)&sm[OFF_BA + l * H_ + col];
#pragma unroll
            for (int i = 0; i < 8; i++) acc[i] = bv;
        }
        mm64<true>(sm, OFF_XS, OFF_WA, rb, col, acc);
#pragma unroll
        for (int i = 0; i < 8; i++) {
            float4 rv = make_float4(fmaxf(acc[i].x, 0.f), fmaxf(acc[i].y, 0.f),
                                    fmaxf(acc[i].z, 0.f), fmaxf(acc[i].w, 0.f));
            store4(&sm[OFF_HS + rb[i] + col], rv);
        }
        __syncthreads();

        // Y-stage: x = relu(h) @ Wb + bb + x  (in place, own elements only)
        {
            float4 bv = *(const float4*)&sm[OFF_BB + l * H_ + col];
#pragma unroll
            for (int i = 0; i < 8; i++) {
                acc[i].x = sm[OFF_XS + rb[i] + col + 0] + bv.x;
                acc[i].y = sm[OFF_XS + rb[i] + col + 1] + bv.y;
                acc[i].z = sm[OFF_XS + rb[i] + col + 2] + bv.z;
                acc[i].w = sm[OFF_XS + rb[i] + col + 3] + bv.w;
            }
        }
        mm64<false>(sm, OFF_HS, OFF_WB, rb, col, acc);  // HS already relu'd
#pragma unroll
        for (int i = 0; i < 8; i++) store4(&sm[OFF_XS + rb[i] + col], acc[i]);
    }
    __syncthreads();

    // =================== output head ===================
    if (tid < TP) {
        float acc = sm[OFF_POS + 3];  // bout
        const float* xr = &sm[OFF_XS + tid * XLD];
#pragma unroll 8
        for (int j = 0; j < H_; j++) acc += fmaxf(xr[j], 0.f) * sm[OFF_WOUT + j];
        out[(size_t)b * P_ + p0 + tid] = acc;
    }
}

// =====================================================================
// Launch
// Inputs (metadata order): z, pos, p, W_feat, W_dir, W0, b0, Wa, ba, Wb, bb, Wout, bout
// =====================================================================
extern "C" void kernel_launch(void* const* d_in, const int* in_sizes, int n_in,
                              void* d_out, int out_size) {
    const float* z      = (const float*)d_in[0];
    const float* pos    = (const float*)d_in[1];
    const float* p      = (const float*)d_in[2];
    const float* W_feat = (const float*)d_in[3];
    const float* W_dir  = (const float*)d_in[4];
    const float* W0     = (const float*)d_in[5];
    const float* b0     = (const float*)d_in[6];
    const float* Wa     = (const float*)d_in[7];
    const float* ba     = (const float*)d_in[8];
    const float* Wb     = (const float*)d_in[9];
    const float* bb     = (const float*)d_in[10];
    const float* Wout   = (const float*)d_in[11];
    const float* bout   = (const float*)d_in[12];
    float* out = (float*)d_out;

    // Set the >48KB dynamic-smem opt-in only OUTSIDE graph capture. The
    // attribute is sticky per function+device, so setting it on the
    // (uncaptured) correctness call covers all later captured replays.
    // This keeps the captured path to pure kernel launches.
    cudaStreamCaptureStatus cap = cudaStreamCaptureStatusNone;
    cudaStreamIsCapturing((cudaStream_t)0, &cap);
    if (cap == cudaStreamCaptureStatusNone) {
        cudaFuncSetAttribute(vson_decoder_kernel,
                             cudaFuncAttributeMaxDynamicSharedMemorySize, SMEM_BYTES);
    }

    vson_precompute_kernel<<<B_ * C_, 64>>>(z, W_feat, W_dir, W0, b0);

    dim3 grid(P_ / TP, B_);
    vson_decoder_kernel<<<grid, 256, SMEM_BYTES>>>(p, pos, W0, Wa, ba, Wb, bb,
                                                   Wout, bout, out);
}

// round 13
// speedup vs baseline: 1.0054x; 1.0054x over previous
#include <cuda_runtime.h>
#include <math.h>

// Shapes (fixed for this problem)
#define B_ 4
#define P_ 32768
#define C_ 8
#define F_ 32
#define D_ 64
#define H_ 64

#define TP 128        // points per CTA tile
#define XLD 68        // padded row stride (floats); multiple of 4 -> float4-aligned rows

// ---- precomputed per-(b,c) data (tiny scratch; __device__ globals, no allocs) ----
__device__ float g_M[B_ * C_ * 3 * H_];   // M[b,c][i][h] = (W_feat @ z[b,c] @ W0_mid)[i,h]
__device__ float g_zi[B_ * C_ * H_];      // zi_proj[b,c][h] = z_inv @ W0[65:129] + b0
__device__ float g_G[16];                 // G = W_feat @ W_feat^T (3x3, padded)

// ---- shared memory layout (in floats) ----
#define OFF_XS   0
#define OFF_HS   (TP * XLD)                 // 8704
#define OFF_WA   (2 * TP * XLD)             // 17408
#define OFF_WB   (OFF_WA + H_ * H_)         // 21504
#define OFF_QS   (OFF_WB + H_ * H_)         // 25600  (q0,q1,q2,s per point)
#define OFF_M    (OFF_QS + TP * 4)          // 26112
#define OFF_ZI   (OFF_M + C_ * 3 * H_)      // 27648
#define OFF_W0   (OFF_ZI + C_ * H_)         // 28160  (W0 row 0)
#define OFF_WOUT (OFF_W0 + H_)              // 28224
#define SMEM_FLOATS (OFF_WOUT + H_)         // 28288
#define SMEM_BYTES  (SMEM_FLOATS * 4)       // 113152 B -> 2 CTAs/SM (with 1KB/CTA reserve)

// =====================================================================
// Precompute kernel: 32 blocks (one per (b,c)), 64 threads (h index)
// =====================================================================
__global__ void vson_precompute_kernel(const float* __restrict__ z,
                                       const float* __restrict__ W_feat,
                                       const float* __restrict__ W_dir,
                                       const float* __restrict__ W0,
                                       const float* __restrict__ b0) {
    __shared__ float s_zinv[D_];
    __shared__ float s_Z0[F_ * H_];

    const int bc = blockIdx.x;          // b*C + c
    const int e = threadIdx.x;          // 0..63
    const float* zb = z + bc * F_ * D_; // z[b,c] : (F, D) row-major

    // z_inv[e] = sum_f z[f,e] * (sum_d z[f,d] * W_dir[d,e])
    float zi = 0.f;
    for (int f = 0; f < F_; f++) {
        float zd = 0.f;
        for (int d = 0; d < D_; d++) zd += zb[f * D_ + d] * W_dir[d * D_ + e];
        zi += zb[f * D_ + e] * zd;
    }
    s_zinv[e] = zi;
    __syncthreads();

    // zi_proj[h] = sum_d z_inv[d] * W0[1+D+d, h] + b0[h]
    {
        float zp = b0[e];
        for (int d = 0; d < D_; d++) zp += s_zinv[d] * W0[(1 + D_ + d) * H_ + e];
        g_zi[bc * H_ + e] = zp;
    }

    // Z0[f,h] = sum_d z[f,d] * W0[1+d, h]
    for (int f = 0; f < F_; f++) {
        float s = 0.f;
        for (int d = 0; d < D_; d++) s += zb[f * D_ + d] * W0[(1 + d) * H_ + e];
        s_Z0[f * H_ + e] = s;
    }
    __syncthreads();

    // M[i,h] = sum_f W_feat[i,f] * Z0[f,h]
    for (int i = 0; i < 3; i++) {
        float s = 0.f;
        for (int f = 0; f < F_; f++) s += W_feat[i * F_ + f] * s_Z0[f * H_ + e];
        g_M[(bc * 3 + i) * H_ + e] = s;
    }

    // G (3x3) once
    if (bc == 0 && e < 9) {
        int i = e / 3, j = e % 3;
        float s = 0.f;
        for (int f = 0; f < F_; f++) s += W_feat[i * F_ + f] * W_feat[j * F_ + f];
        g_G[e] = s;
    }
}

// =====================================================================
// Main kernel helpers
// =====================================================================
// acc[i] += act(in[rb[i]+k]) * W[k][col..col+3]  over k=0..63, float4 loads.
// RELU=true applies relu to the activation read; RELU=false consumes raw
// (used when the producer already stored relu'd values).
template <bool RELU>
__device__ __forceinline__ void mm64v(const float* __restrict__ smem,
                                      int in_off, int w_off,
                                      const int rb[8], int col,
                                      float4 acc[8]) {
    for (int k0 = 0; k0 < H_; k0 += 4) {
        float4 a[8];
#pragma unroll
        for (int i = 0; i < 8; i++) {
            a[i] = *(const float4*)(smem + in_off + rb[i] + k0);
            if (RELU) {
                a[i].x = fmaxf(a[i].x, 0.f);
                a[i].y = fmaxf(a[i].y, 0.f);
                a[i].z = fmaxf(a[i].z, 0.f);
                a[i].w = fmaxf(a[i].w, 0.f);
            }
        }
#pragma unroll
        for (int kk = 0; kk < 4; kk++) {
            float4 w = *(const float4*)(smem + w_off + (k0 + kk) * H_ + col);
#pragma unroll
            for (int i = 0; i < 8; i++) {
                float r = (kk == 0) ? a[i].x : (kk == 1) ? a[i].y
                        : (kk == 2) ? a[i].z : a[i].w;
                acc[i].x += r * w.x;
                acc[i].y += r * w.y;
                acc[i].z += r * w.z;
                acc[i].w += r * w.w;
            }
        }
    }
}

// =====================================================================
// Main decoder kernel: grid (P/TP, B), 256 threads
// Thread tile: 8 points x 4 columns (tj = tid&15 -> cols, tp = tid>>4 -> rows)
// =====================================================================
__global__ __launch_bounds__(256, 2)
void vson_decoder_kernel(const float* __restrict__ p,
                         const float* __restrict__ pos,
                         const float* __restrict__ W0,
                         const float* __restrict__ Wa,
                         const float* __restrict__ ba,
                         const float* __restrict__ Wb,
                         const float* __restrict__ bb,
                         const float* __restrict__ Wout,
                         const float* __restrict__ bout,
                         float* __restrict__ out) {
    extern __shared__ float sm[];
    const int tid = threadIdx.x;
    const int b = blockIdx.y;
    const int p0 = blockIdx.x * TP;

    // ---- stage block-0 weights + misc into shared ----
    {
        const float4* sa = (const float4*)Wa;   // layer 0
        const float4* sb = (const float4*)Wb;
        float4* dA = (float4*)&sm[OFF_WA];
        float4* dB = (float4*)&sm[OFF_WB];
        for (int i = tid; i < (H_ * H_) / 4; i += 256) { dA[i] = sa[i]; dB[i] = sb[i]; }
    }
    for (int i = tid; i < C_ * 3 * H_; i += 256) sm[OFF_M + i] = g_M[b * C_ * 3 * H_ + i];
    for (int i = tid; i < C_ * H_; i += 256)     sm[OFF_ZI + i] = g_zi[b * C_ * H_ + i];
    if (tid < H_) { sm[OFF_W0 + tid] = W0[tid]; sm[OFF_WOUT + tid] = Wout[tid]; }
    __syncthreads();

    // ---- per-point q (centered+clamped) and scalar s = |p_ext|^2 ----
    if (tid < TP) {
        const int pt = p0 + tid;
        const float* pp = p + ((size_t)b * P_ + pt) * 3;
        float q0 = pp[0] - pos[b * 3 + 0];
        float q1 = pp[1] - pos[b * 3 + 1];
        float q2 = pp[2] - pos[b * 3 + 2];
        float n = sqrtf(q0 * q0 + q1 * q1 + q2 * q2);
        if (n > 0.5f) { float sc = 0.5f / n; q0 *= sc; q1 *= sc; q2 *= sc; }
        float s = g_G[0] * q0 * q0 + g_G[4] * q1 * q1 + g_G[8] * q2 * q2
                + (g_G[1] + g_G[3]) * q0 * q1
                + (g_G[2] + g_G[6]) * q0 * q2
                + (g_G[5] + g_G[7]) * q1 * q2;
        ((float4*)&sm[OFF_QS])[tid] = make_float4(q0, q1, q2, s);
    }
    __syncthreads();

    const int tj = tid & 15;
    const int tp = tid >> 4;
    const int col = 4 * tj;
    int rb[8];
#pragma unroll
    for (int i = 0; i < 8; i++) rb[i] = (8 * tp + i) * XLD;

    float4 pool[8];

    // =================== block 0 over C=8, with max-pool ===================
    for (int c = 0; c < C_; c++) {
        // X-stage: x = s*W0row0 + q.M[c] + zi_proj[c]   (raw x kept for residual)
        {
            float4 w0 = *(const float4*)&sm[OFF_W0 + col];
            float4 m0 = *(const float4*)&sm[OFF_M + (c * 3 + 0) * H_ + col];
            float4 m1 = *(const float4*)&sm[OFF_M + (c * 3 + 1) * H_ + col];
            float4 m2 = *(const float4*)&sm[OFF_M + (c * 3 + 2) * H_ + col];
            float4 zz = *(const float4*)&sm[OFF_ZI + c * H_ + col];
#pragma unroll
            for (int i = 0; i < 8; i++) {
                float4 q = ((const float4*)&sm[OFF_QS])[8 * tp + i];
                float4 v;
                v.x = q.w * w0.x + q.x * m0.x + q.y * m1.x + q.z * m2.x + zz.x;
                v.y = q.w * w0.y + q.x * m0.y + q.y * m1.y + q.z * m2.y + zz.y;
                v.z = q.w * w0.z + q.x * m0.z + q.y * m1.z + q.z * m2.z + zz.z;
                v.w = q.w * w0.w + q.x * m0.w + q.y * m1.w + q.z * m2.w + zz.w;
                *(float4*)&sm[OFF_XS + rb[i] + col] = v;
            }
        }
        __syncthreads();

        // H-stage: h = relu(x) @ Wa0 + ba0 ; store relu(h) (h only consumed via relu)
        float4 acc[8];
        {
            float4 bv = *(const float4*)(ba + col);
#pragma unroll
            for (int i = 0; i < 8; i++) acc[i] = bv;
        }
        mm64v<true>(sm, OFF_XS, OFF_WA, rb, col, acc);
#pragma unroll
        for (int i = 0; i < 8; i++) {
            float4 rv = make_float4(fmaxf(acc[i].x, 0.f), fmaxf(acc[i].y, 0.f),
                                    fmaxf(acc[i].z, 0.f), fmaxf(acc[i].w, 0.f));
            *(float4*)&sm[OFF_HS + rb[i] + col] = rv;
        }
        __syncthreads();

        // Y-stage: y = relu(h) @ Wb0 + bb0 + x ; pool = max(pool, y)
        {
            float4 bv = *(const float4*)(bb + col);
#pragma unroll
            for (int i = 0; i < 8; i++) {
                float4 xv = *(const float4*)&sm[OFF_XS + rb[i] + col];
                acc[i].x = xv.x + bv.x;
                acc[i].y = xv.y + bv.y;
                acc[i].z = xv.z + bv.z;
                acc[i].w = xv.w + bv.w;
            }
        }
        mm64v<false>(sm, OFF_HS, OFF_WB, rb, col, acc);  // HS already relu'd
        if (c == 0) {
#pragma unroll
            for (int i = 0; i < 8; i++) pool[i] = acc[i];
        } else {
#pragma unroll
            for (int i = 0; i < 8; i++) {
                pool[i].x = fmaxf(pool[i].x, acc[i].x);
                pool[i].y = fmaxf(pool[i].y, acc[i].y);
                pool[i].z = fmaxf(pool[i].z, acc[i].z);
                pool[i].w = fmaxf(pool[i].w, acc[i].w);
            }
        }
        // no sync needed here: next X-stage writes only this thread's own (p,col)
        // elements of XS; other threads' Y-stages read only HS + their own XS,
        // and H-stage (which rewrites HS) sits behind the post-X-stage barrier.
    }

    // pooled -> xs
#pragma unroll
    for (int i = 0; i < 8; i++) *(float4*)&sm[OFF_XS + rb[i] + col] = pool[i];
    __syncthreads();

    // =================== residual blocks 1..4 ===================
    for (int l = 1; l < 5; l++) {
        __syncthreads();  // orders prior Y xs-writes & WB reads vs. restage
        {
            const float4* sa = (const float4*)(Wa + l * H_ * H_);
            const float4* sb = (const float4*)(Wb + l * H_ * H_);
            float4* dA = (float4*)&sm[OFF_WA];
            float4* dB = (float4*)&sm[OFF_WB];
            for (int i = tid; i < (H_ * H_) / 4; i += 256) { dA[i] = sa[i]; dB[i] = sb[i]; }
        }
        __syncthreads();

        // H-stage: store relu(h)
        float4 acc[8];
        {
            float4 bv = *(const float4*)(ba + l * H_ + col);
#pragma unroll
            for (int i = 0; i < 8; i++) acc[i] = bv;
        }
        mm64v<true>(sm, OFF_XS, OFF_WA, rb, col, acc);
#pragma unroll
        for (int i = 0; i < 8; i++) {
            float4 rv = make_float4(fmaxf(acc[i].x, 0.f), fmaxf(acc[i].y, 0.f),
                                    fmaxf(acc[i].z, 0.f), fmaxf(acc[i].w, 0.f));
            *(float4*)&sm[OFF_HS + rb[i] + col] = rv;
        }
        __syncthreads();

        // Y-stage: x = relu(h) @ Wb + bb + x  (in place, own elements only)
        {
            float4 bv = *(const float4*)(bb + l * H_ + col);
#pragma unroll
            for (int i = 0; i < 8; i++) {
                float4 xv = *(const float4*)&sm[OFF_XS + rb[i] + col];
                acc[i].x = xv.x + bv.x;
                acc[i].y = xv.y + bv.y;
                acc[i].z = xv.z + bv.z;
                acc[i].w = xv.w + bv.w;
            }
        }
        mm64v<false>(sm, OFF_HS, OFF_WB, rb, col, acc);  // HS already relu'd
#pragma unroll
        for (int i = 0; i < 8; i++) *(float4*)&sm[OFF_XS + rb[i] + col] = acc[i];
    }
    __syncthreads();

    // =================== output head ===================
    if (tid < TP) {
        float acc = bout[0];
        const float4* xr = (const float4*)&sm[OFF_XS + tid * XLD];
        const float4* wv = (const float4*)&sm[OFF_WOUT];
#pragma unroll
        for (int j = 0; j < H_ / 4; j++) {
            float4 x4 = xr[j];
            float4 w4 = wv[j];
            acc += fmaxf(x4.x, 0.f) * w4.x + fmaxf(x4.y, 0.f) * w4.y
                 + fmaxf(x4.z, 0.f) * w4.z + fmaxf(x4.w, 0.f) * w4.w;
        }
        out[(size_t)b * P_ + p0 + tid] = acc;
    }
}

// =====================================================================
// Launch
// Inputs (metadata order): z, pos, p, W_feat, W_dir, W0, b0, Wa, ba, Wb, bb, Wout, bout
// =====================================================================
extern "C" void kernel_launch(void* const* d_in, const int* in_sizes, int n_in,
                              void* d_out, int out_size) {
    const float* z      = (const float*)d_in[0];
    const float* pos    = (const float*)d_in[1];
    const float* p      = (const float*)d_in[2];
    const float* W_feat = (const float*)d_in[3];
    const float* W_dir  = (const float*)d_in[4];
    const float* W0     = (const float*)d_in[5];
    const float* b0     = (const float*)d_in[6];
    const float* Wa     = (const float*)d_in[7];
    const float* ba     = (const float*)d_in[8];
    const float* Wb     = (const float*)d_in[9];
    const float* bb     = (const float*)d_in[10];
    const float* Wout   = (const float*)d_in[11];
    const float* bout   = (const float*)d_in[12];
    float* out = (float*)d_out;

    // Set the >48KB dynamic-smem opt-in only OUTSIDE graph capture. The
    // attribute is sticky per function+device, so setting it on the
    // (uncaptured) correctness call covers all later captured replays.
    cudaStreamCaptureStatus cap = cudaStreamCaptureStatusNone;
    cudaStreamIsCapturing((cudaStream_t)0, &cap);
    if (cap == cudaStreamCaptureStatusNone) {
        cudaFuncSetAttribute(vson_decoder_kernel,
                             cudaFuncAttributeMaxDynamicSharedMemorySize, SMEM_BYTES);
    }

    vson_precompute_kernel<<<B_ * C_, 64>>>(z, W_feat, W_dir, W0, b0);

    dim3 grid(P_ / TP, B_);
    vson_decoder_kernel<<<grid, 256, SMEM_BYTES>>>(p, pos, W0, Wa, ba, Wb, bb,
                                                   Wout, bout, out);
}

// round 14
// speedup vs baseline: 1.0780x; 1.0722x over previous
#include <cuda_runtime.h>
#include <math.h>

// Shapes (fixed for this problem)
#define B_ 4
#define P_ 32768
#define C_ 8
#define F_ 32
#define D_ 64
#define H_ 64

#define TP 128        // points per CTA tile
#define XLD 68        // padded row stride (floats); multiple of 4 -> float4-aligned rows

// ---- precomputed per-(b,c) data (tiny scratch; __device__ globals, no allocs) ----
__device__ float g_M[B_ * C_ * 3 * H_];   // M[b,c][i][h] = (W_feat @ z[b,c] @ W0_mid)[i,h]
__device__ float g_zi[B_ * C_ * H_];      // zi_proj[b,c][h] = z_inv @ W0[65:129] + b0
__device__ float g_G[16];                 // G = W_feat @ W_feat^T (3x3, padded)

// ---- shared memory layout (in floats) ----
#define OFF_XS   0
#define OFF_HS   (TP * XLD)                 // 8704
#define OFF_WA   (2 * TP * XLD)             // 17408
#define OFF_WB   (OFF_WA + H_ * H_)         // 21504
#define OFF_QS   (OFF_WB + H_ * H_)         // 25600  (q0,q1,q2,s per point)
#define OFF_M    (OFF_QS + TP * 4)          // 26112
#define OFF_ZI   (OFF_M + C_ * 3 * H_)      // 27648
#define OFF_W0   (OFF_ZI + C_ * H_)         // 28160  (W0 row 0)
#define OFF_WOUT (OFF_W0 + H_)              // 28224
#define SMEM_FLOATS (OFF_WOUT + H_)         // 28288
#define SMEM_BYTES  (SMEM_FLOATS * 4)       // 113152 B -> 2 CTAs/SM (with 1KB/CTA reserve)

// =====================================================================
// Precompute kernel: 32 blocks (one per (b,c)), 64 threads (h index)
// =====================================================================
__global__ void vson_precompute_kernel(const float* __restrict__ z,
                                       const float* __restrict__ W_feat,
                                       const float* __restrict__ W_dir,
                                       const float* __restrict__ W0,
                                       const float* __restrict__ b0) {
    __shared__ float s_zinv[D_];
    __shared__ float s_Z0[F_ * H_];

    const int bc = blockIdx.x;          // b*C + c
    const int e = threadIdx.x;          // 0..63
    const float* zb = z + bc * F_ * D_; // z[b,c] : (F, D) row-major

    // z_inv[e] = sum_f z[f,e] * (sum_d z[f,d] * W_dir[d,e])
    float zi = 0.f;
    for (int f = 0; f < F_; f++) {
        float zd = 0.f;
        for (int d = 0; d < D_; d++) zd += zb[f * D_ + d] * W_dir[d * D_ + e];
        zi += zb[f * D_ + e] * zd;
    }
    s_zinv[e] = zi;
    __syncthreads();

    // zi_proj[h] = sum_d z_inv[d] * W0[1+D+d, h] + b0[h]
    {
        float zp = b0[e];
        for (int d = 0; d < D_; d++) zp += s_zinv[d] * W0[(1 + D_ + d) * H_ + e];
        g_zi[bc * H_ + e] = zp;
    }

    // Z0[f,h] = sum_d z[f,d] * W0[1+d, h]
    for (int f = 0; f < F_; f++) {
        float s = 0.f;
        for (int d = 0; d < D_; d++) s += zb[f * D_ + d] * W0[(1 + d) * H_ + e];
        s_Z0[f * H_ + e] = s;
    }
    __syncthreads();

    // M[i,h] = sum_f W_feat[i,f] * Z0[f,h]
    for (int i = 0; i < 3; i++) {
        float s = 0.f;
        for (int f = 0; f < F_; f++) s += W_feat[i * F_ + f] * s_Z0[f * H_ + e];
        g_M[(bc * 3 + i) * H_ + e] = s;
    }

    // G (3x3) once
    if (bc == 0 && e < 9) {
        int i = e / 3, j = e % 3;
        float s = 0.f;
        for (int f = 0; f < F_; f++) s += W_feat[i * F_ + f] * W_feat[j * F_ + f];
        g_G[e] = s;
    }
}

// =====================================================================
// f32x2 packed helpers (Blackwell native FFMA2 path)
// =====================================================================
__device__ __forceinline__ unsigned long long pack2(float lo, float hi) {
    unsigned long long r;
    asm("mov.b64 %0, {%1, %2};" : "=l"(r) : "f"(lo), "f"(hi));
    return r;
}
__device__ __forceinline__ void unpack2(unsigned long long v, float& lo, float& hi) {
    asm("mov.b64 {%0, %1}, %2;" : "=f"(lo), "=f"(hi) : "l"(v));
}
// acc = a*b + acc, lanewise on packed f32x2 (one FFMA2 instruction)
__device__ __forceinline__ void ffma2(unsigned long long& acc,
                                      unsigned long long a,
                                      unsigned long long b) {
    asm("fma.rn.f32x2 %0, %1, %2, %0;" : "+l"(acc) : "l"(a), "l"(b));
}

// =====================================================================
// Packed GEMV: acc{01,23}[i] += act(in[rb[i]+k]) * W[k][col..col+3], k=0..63
// RELU=true applies relu to the activation read; RELU=false consumes raw
// (used when the producer already stored relu'd values).
// =====================================================================
template <bool RELU>
__device__ __forceinline__ void mm64p(const float* __restrict__ smem,
                                      int in_off, int w_off,
                                      const int rb[8], int col,
                                      unsigned long long acc01[8],
                                      unsigned long long acc23[8]) {
    for (int k0 = 0; k0 < H_; k0 += 4) {
        float4 a[8];
#pragma unroll
        for (int i = 0; i < 8; i++) {
            a[i] = *(const float4*)(smem + in_off + rb[i] + k0);
            if (RELU) {
                a[i].x = fmaxf(a[i].x, 0.f);
                a[i].y = fmaxf(a[i].y, 0.f);
                a[i].z = fmaxf(a[i].z, 0.f);
                a[i].w = fmaxf(a[i].w, 0.f);
            }
        }
#pragma unroll
        for (int kk = 0; kk < 4; kk++) {
            // LDS.128 of weights: consecutive regs already hold {c0,c1},{c2,c3}
            const ulonglong2 w =
                *(const ulonglong2*)(smem + w_off + (k0 + kk) * H_ + col);
#pragma unroll
            for (int i = 0; i < 8; i++) {
                float r = (kk == 0) ? a[i].x : (kk == 1) ? a[i].y
                        : (kk == 2) ? a[i].z : a[i].w;
                unsigned long long rr = pack2(r, r);
                ffma2(acc01[i], w.x, rr);
                ffma2(acc23[i], w.y, rr);
            }
        }
    }
}

// =====================================================================
// Main decoder kernel: grid (P/TP, B), 256 threads
// Thread tile: 8 points x 4 columns (tj = tid&15 -> cols, tp = tid>>4 -> rows)
// =====================================================================
__global__ __launch_bounds__(256, 2)
void vson_decoder_kernel(const float* __restrict__ p,
                         const float* __restrict__ pos,
                         const float* __restrict__ W0,
                         const float* __restrict__ Wa,
                         const float* __restrict__ ba,
                         const float* __restrict__ Wb,
                         const float* __restrict__ bb,
                         const float* __restrict__ Wout,
                         const float* __restrict__ bout,
                         float* __restrict__ out) {
    extern __shared__ float sm[];
    const int tid = threadIdx.x;
    const int b = blockIdx.y;
    const int p0 = blockIdx.x * TP;

    // ---- stage block-0 weights + misc into shared ----
    {
        const float4* sa = (const float4*)Wa;   // layer 0
        const float4* sb = (const float4*)Wb;
        float4* dA = (float4*)&sm[OFF_WA];
        float4* dB = (float4*)&sm[OFF_WB];
        for (int i = tid; i < (H_ * H_) / 4; i += 256) { dA[i] = sa[i]; dB[i] = sb[i]; }
    }
    for (int i = tid; i < C_ * 3 * H_; i += 256) sm[OFF_M + i] = g_M[b * C_ * 3 * H_ + i];
    for (int i = tid; i < C_ * H_; i += 256)     sm[OFF_ZI + i] = g_zi[b * C_ * H_ + i];
    if (tid < H_) { sm[OFF_W0 + tid] = W0[tid]; sm[OFF_WOUT + tid] = Wout[tid]; }
    __syncthreads();

    // ---- per-point q (centered+clamped) and scalar s = |p_ext|^2 ----
    if (tid < TP) {
        const int pt = p0 + tid;
        const float* pp = p + ((size_t)b * P_ + pt) * 3;
        float q0 = pp[0] - pos[b * 3 + 0];
        float q1 = pp[1] - pos[b * 3 + 1];
        float q2 = pp[2] - pos[b * 3 + 2];
        float n = sqrtf(q0 * q0 + q1 * q1 + q2 * q2);
        if (n > 0.5f) { float sc = 0.5f / n; q0 *= sc; q1 *= sc; q2 *= sc; }
        float s = g_G[0] * q0 * q0 + g_G[4] * q1 * q1 + g_G[8] * q2 * q2
                + (g_G[1] + g_G[3]) * q0 * q1
                + (g_G[2] + g_G[6]) * q0 * q2
                + (g_G[5] + g_G[7]) * q1 * q2;
        ((float4*)&sm[OFF_QS])[tid] = make_float4(q0, q1, q2, s);
    }
    __syncthreads();

    const int tj = tid & 15;
    const int tp = tid >> 4;
    const int col = 4 * tj;
    int rb[8];
#pragma unroll
    for (int i = 0; i < 8; i++) rb[i] = (8 * tp + i) * XLD;

    float4 pool[8];

    // =================== block 0 over C=8, with max-pool ===================
    for (int c = 0; c < C_; c++) {
        // X-stage: x = s*W0row0 + q.M[c] + zi_proj[c]   (raw x kept for residual)
        {
            float4 w0 = *(const float4*)&sm[OFF_W0 + col];
            float4 m0 = *(const float4*)&sm[OFF_M + (c * 3 + 0) * H_ + col];
            float4 m1 = *(const float4*)&sm[OFF_M + (c * 3 + 1) * H_ + col];
            float4 m2 = *(const float4*)&sm[OFF_M + (c * 3 + 2) * H_ + col];
            float4 zz = *(const float4*)&sm[OFF_ZI + c * H_ + col];
#pragma unroll
            for (int i = 0; i < 8; i++) {
                float4 q = ((const float4*)&sm[OFF_QS])[8 * tp + i];
                float4 v;
                v.x = q.w * w0.x + q.x * m0.x + q.y * m1.x + q.z * m2.x + zz.x;
                v.y = q.w * w0.y + q.x * m0.y + q.y * m1.y + q.z * m2.y + zz.y;
                v.z = q.w * w0.z + q.x * m0.z + q.y * m1.z + q.z * m2.z + zz.z;
                v.w = q.w * w0.w + q.x * m0.w + q.y * m1.w + q.z * m2.w + zz.w;
                *(float4*)&sm[OFF_XS + rb[i] + col] = v;
            }
        }
        __syncthreads();

        // H-stage: h = relu(x) @ Wa0 + ba0 ; store relu(h) (h only consumed via relu)
        unsigned long long acc01[8], acc23[8];
        {
            float4 bv = *(const float4*)(ba + col);
            unsigned long long b01 = pack2(bv.x, bv.y);
            unsigned long long b23 = pack2(bv.z, bv.w);
#pragma unroll
            for (int i = 0; i < 8; i++) { acc01[i] = b01; acc23[i] = b23; }
        }
        mm64p<true>(sm, OFF_XS, OFF_WA, rb, col, acc01, acc23);
#pragma unroll
        for (int i = 0; i < 8; i++) {
            float4 v;
            unpack2(acc01[i], v.x, v.y);
            unpack2(acc23[i], v.z, v.w);
            v.x = fmaxf(v.x, 0.f); v.y = fmaxf(v.y, 0.f);
            v.z = fmaxf(v.z, 0.f); v.w = fmaxf(v.w, 0.f);
            *(float4*)&sm[OFF_HS + rb[i] + col] = v;
        }
        __syncthreads();

        // Y-stage: y = relu(h) @ Wb0 + bb0 + x ; pool = max(pool, y)
        {
            float4 bv = *(const float4*)(bb + col);
#pragma unroll
            for (int i = 0; i < 8; i++) {
                float4 xv = *(const float4*)&sm[OFF_XS + rb[i] + col];
                acc01[i] = pack2(xv.x + bv.x, xv.y + bv.y);
                acc23[i] = pack2(xv.z + bv.z, xv.w + bv.w);
            }
        }
        mm64p<false>(sm, OFF_HS, OFF_WB, rb, col, acc01, acc23);  // HS already relu'd
#pragma unroll
        for (int i = 0; i < 8; i++) {
            float4 v;
            unpack2(acc01[i], v.x, v.y);
            unpack2(acc23[i], v.z, v.w);
            if (c == 0) {
                pool[i] = v;
            } else {
                pool[i].x = fmaxf(pool[i].x, v.x);
                pool[i].y = fmaxf(pool[i].y, v.y);
                pool[i].z = fmaxf(pool[i].z, v.z);
                pool[i].w = fmaxf(pool[i].w, v.w);
            }
        }
        // no sync needed here: next X-stage writes only this thread's own (p,col)
        // elements of XS; other threads' Y-stages read only HS + their own XS,
        // and H-stage (which rewrites HS) sits behind the post-X-stage barrier.
    }

    // pooled -> xs
#pragma unroll
    for (int i = 0; i < 8; i++) *(float4*)&sm[OFF_XS + rb[i] + col] = pool[i];
    __syncthreads();

    // =================== residual blocks 1..4 ===================
    for (int l = 1; l < 5; l++) {
        __syncthreads();  // orders prior Y xs-writes & WB reads vs. restage
        {
            const float4* sa = (const float4*)(Wa + l * H_ * H_);
            const float4* sb = (const float4*)(Wb + l * H_ * H_);
            float4* dA = (float4*)&sm[OFF_WA];
            float4* dB = (float4*)&sm[OFF_WB];
            for (int i = tid; i < (H_ * H_) / 4; i += 256) { dA[i] = sa[i]; dB[i] = sb[i]; }
        }
        __syncthreads();

        // H-stage: store relu(h)
        unsigned long long acc01[8], acc23[8];
        {
            float4 bv = *(const float4*)(ba + l * H_ + col);
            unsigned long long b01 = pack2(bv.x, bv.y);
            unsigned long long b23 = pack2(bv.z, bv.w);
#pragma unroll
            for (int i = 0; i < 8; i++) { acc01[i] = b01; acc23[i] = b23; }
        }
        mm64p<true>(sm, OFF_XS, OFF_WA, rb, col, acc01, acc23);
#pragma unroll
        for (int i = 0; i < 8; i++) {
            float4 v;
            unpack2(acc01[i], v.x, v.y);
            unpack2(acc23[i], v.z, v.w);
            v.x = fmaxf(v.x, 0.f); v.y = fmaxf(v.y, 0.f);
            v.z = fmaxf(v.z, 0.f); v.w = fmaxf(v.w, 0.f);
            *(float4*)&sm[OFF_HS + rb[i] + col] = v;
        }
        __syncthreads();

        // Y-stage: x = relu(h) @ Wb + bb + x  (in place, own elements only)
        {
            float4 bv = *(const float4*)(bb + l * H_ + col);
#pragma unroll
            for (int i = 0; i < 8; i++) {
                float4 xv = *(const float4*)&sm[OFF_XS + rb[i] + col];
                acc01[i] = pack2(xv.x + bv.x, xv.y + bv.y);
                acc23[i] = pack2(xv.z + bv.z, xv.w + bv.w);
            }
        }
        mm64p<false>(sm, OFF_HS, OFF_WB, rb, col, acc01, acc23);  // HS already relu'd
#pragma unroll
        for (int i = 0; i < 8; i++) {
            float4 v;
            unpack2(acc01[i], v.x, v.y);
            unpack2(acc23[i], v.z, v.w);
            *(float4*)&sm[OFF_XS + rb[i] + col] = v;
        }
    }
    __syncthreads();

    // =================== output head ===================
    if (tid < TP) {
        float acc = bout[0];
        const float4* xr = (const float4*)&sm[OFF_XS + tid * XLD];
        const float4* wv = (const float4*)&sm[OFF_WOUT];
#pragma unroll
        for (int j = 0; j < H_ / 4; j++) {
            float4 x4 = xr[j];
            float4 w4 = wv[j];
            acc += fmaxf(x4.x, 0.f) * w4.x + fmaxf(x4.y, 0.f) * w4.y
                 + fmaxf(x4.z, 0.f) * w4.z + fmaxf(x4.w, 0.f) * w4.w;
        }
        out[(size_t)b * P_ + p0 + tid] = acc;
    }
}

// =====================================================================
// Launch
// Inputs (metadata order): z, pos, p, W_feat, W_dir, W0, b0, Wa, ba, Wb, bb, Wout, bout
// =====================================================================
extern "C" void kernel_launch(void* const* d_in, const int* in_sizes, int n_in,
                              void* d_out, int out_size) {
    const float* z      = (const float*)d_in[0];
    const float* pos    = (const float*)d_in[1];
    const float* p      = (const float*)d_in[2];
    const float* W_feat = (const float*)d_in[3];
    const float* W_dir  = (const float*)d_in[4];
    const float* W0     = (const float*)d_in[5];
    const float* b0     = (const float*)d_in[6];
    const float* Wa     = (const float*)d_in[7];
    const float* ba     = (const float*)d_in[8];
    const float* Wb     = (const float*)d_in[9];
    const float* bb     = (const float*)d_in[10];
    const float* Wout   = (const float*)d_in[11];
    const float* bout   = (const float*)d_in[12];
    float* out = (float*)d_out;

    // Set the >48KB dynamic-smem opt-in only OUTSIDE graph capture. The
    // attribute is sticky per function+device, so setting it on the
    // (uncaptured) correctness call covers all later captured replays.
    cudaStreamCaptureStatus cap = cudaStreamCaptureStatusNone;
    cudaStreamIsCapturing((cudaStream_t)0, &cap);
    if (cap == cudaStreamCaptureStatusNone) {
        cudaFuncSetAttribute(vson_decoder_kernel,
                             cudaFuncAttributeMaxDynamicSharedMemorySize, SMEM_BYTES);
    }

    vson_precompute_kernel<<<B_ * C_, 64>>>(z, W_feat, W_dir, W0, b0);

    dim3 grid(P_ / TP, B_);
    vson_decoder_kernel<<<grid, 256, SMEM_BYTES>>>(p, pos, W0, Wa, ba, Wb, bb,
                                                   Wout, bout, out);
}